// round 2
// baseline (speedup 1.0000x reference)
#include <cuda_runtime.h>
#include <math.h>

#define LL 160
#define BB 16
#define EE 512
#define CC 256
#define HH 512
#define DM 128
#define DO 512
#define TOK (BB*LL)          /* 2560 */
#define CP 258               /* C + 2 coords */
#define W1C 1028             /* 2*CP + H */
#define KC (3*EE)            /* 1536 conv GEMM K */
#define NT 200               /* pair tiles per batch: 20 l-tiles * 10 m-tiles */
#define PAD 132

/* static device scratch (no runtime allocation allowed) */
__device__ float g_wT[KC*CC];        /* conv weight, k-major [kk*512+e][c] */
__device__ float g_W1T[CP*256];      /* [k][n]: n<128 -> u weights, n>=128 -> v weights */
__device__ float g_W2T[DM*DM];       /* [k][d] */
__device__ float g_W3T[DM*DM];
__device__ float g_W4T[DM*DM];
__device__ float g_y[TOK*CC];        /* conv+lrelu output, token-major */
__device__ float g_scale[CC];
__device__ float g_shift[CC];
__device__ float g_u[TOK*DM];
__device__ float g_v[TOK*DM];
__device__ float g_hw[BB*DM];
__device__ float g_part[BB*NT*DM];   /* deterministic per-tile partial sums */

__device__ __forceinline__ float lrelu(float x){ return x > 0.f ? x : 0.1f*x; }

typedef unsigned long long u64;
__device__ __forceinline__ u64 pk2(float lo, float hi){
    u64 r; asm("mov.b64 %0,{%1,%2};" : "=l"(r) : "f"(lo), "f"(hi)); return r;
}
__device__ __forceinline__ void upk2(u64 v, float &lo, float &hi){
    asm("mov.b64 {%0,%1},%2;" : "=f"(lo), "=f"(hi) : "l"(v));
}
__device__ __forceinline__ u64 ffma2(u64 a, u64 b, u64 c){
    u64 d; asm("fma.rn.f32x2 %0,%1,%2,%3;" : "=l"(d) : "l"(a), "l"(b), "l"(c)); return d;
}

/* ---------------- weight transposes ---------------- */
__global__ void k_prep(const float* __restrict__ conv_w, const float* __restrict__ W1,
                       const float* __restrict__ W2, const float* __restrict__ W3,
                       const float* __restrict__ W4){
    int idx = blockIdx.x*256 + threadIdx.x;
    if (idx < KC*CC){
        int kidx = idx >> 8, c = idx & 255;
        int e = kidx & 511, kk = kidx >> 9;
        g_wT[idx] = conv_w[c*KC + e*3 + kk];
    }
    if (idx < CP*256){
        int k = idx >> 8, n = idx & 255;
        g_W1T[idx] = (n < DM) ? W1[n*W1C + k] : W1[(n-DM)*W1C + CP + k];
    }
    if (idx < DM*DM){
        int k = idx >> 7, d = idx & 127;
        g_W2T[idx] = W2[d*DM + k];
        g_W3T[idx] = W3[d*DM + k];
        g_W4T[idx] = W4[d*DM + k];
    }
}

/* hw[b][d] = sum_c h[b,c] * W1[d, 2*CP + c] */
__global__ void k_hw(const float* __restrict__ h, const float* __restrict__ W1){
    __shared__ float hs[HH];
    int b = blockIdx.x, tid = threadIdx.x;   /* 128 threads */
    for (int i = tid; i < HH; i += 128) hs[i] = h[b*HH + i];
    __syncthreads();
    float acc = 0.f;
    const float* w = W1 + tid*W1C + 2*CP;
    #pragma unroll 8
    for (int c = 0; c < HH; c++) acc += hs[c]*w[c];
    g_hw[b*DM + tid] = acc;
}

/* conv1d k=3 pad=1 as GEMM. block = (16-token tile, b); 256 threads.
   thread: 2 tokens x 8 channels (c = tx + 32*j). */
__global__ void __launch_bounds__(256,1) k_conv(const float* __restrict__ x,
                                                const float* __restrict__ conv_b){
    __shared__ float xs[18*512];   /* rows l0-1 .. l0+16 */
    __shared__ float ws[8*256];
    int l0 = blockIdx.x*16, b = blockIdx.y;
    int tid = threadIdx.x, tx = tid & 31, ty = tid >> 5;
    for (int idx = tid; idx < 18*512; idx += 256){
        int r = idx >> 9, e = idx & 511;
        int l = l0 + r - 1;
        xs[idx] = (l >= 0 && l < LL) ? x[(l*BB + b)*EE + e] : 0.f;
    }
    float acc[2][8];
    #pragma unroll
    for (int i = 0; i < 2; i++)
        #pragma unroll
        for (int j = 0; j < 8; j++) acc[i][j] = 0.f;

    for (int k0 = 0; k0 < KC; k0 += 8){
        __syncthreads();
        for (int idx = tid; idx < 8*256; idx += 256) ws[idx] = g_wT[k0*256 + idx];
        __syncthreads();
        #pragma unroll
        for (int kc = 0; kc < 8; kc++){
            int k = k0 + kc, e = k & 511, kk = k >> 9;
            float a0 = xs[(ty + kk)*512 + e];
            float a1 = xs[(ty + 8 + kk)*512 + e];
            const float* wr = ws + kc*256 + tx;
            #pragma unroll
            for (int j = 0; j < 8; j++){
                float wv = wr[32*j];
                acc[0][j] += a0*wv;
                acc[1][j] += a1*wv;
            }
        }
    }
    #pragma unroll
    for (int i = 0; i < 2; i++){
        int t = b*LL + l0 + ty + 8*i;
        #pragma unroll
        for (int j = 0; j < 8; j++){
            int c = tx + 32*j;
            g_y[t*CC + c] = lrelu(acc[i][j] + conv_b[c]);
        }
    }
}

/* per-channel BN stats folded into scale/shift */
__global__ void k_stats(const float* __restrict__ bn_g, const float* __restrict__ bn_b){
    __shared__ float s1[256], s2[256];
    int c = blockIdx.x, tid = threadIdx.x;
    float a = 0.f, q = 0.f;
    for (int t = tid; t < TOK; t += 256){
        float v = g_y[t*CC + c];
        a += v; q += v*v;
    }
    s1[tid] = a; s2[tid] = q; __syncthreads();
    for (int s = 128; s > 0; s >>= 1){
        if (tid < s){ s1[tid] += s1[tid+s]; s2[tid] += s2[tid+s]; }
        __syncthreads();
    }
    if (tid == 0){
        float mu = s1[0]/(float)TOK;
        float var = s2[0]/(float)TOK - mu*mu;
        float sc = bn_g[c]*rsqrtf(var + 1e-5f);
        g_scale[c] = sc;
        g_shift[c] = bn_b[c] - mu*sc;
    }
}

/* u/v projection: 8 tokens per block, 256 threads (one output column each) */
__global__ void __launch_bounds__(256,4) k_uv(){
    __shared__ float xf[8*260];
    int t0 = blockIdx.x*8;
    int b = t0 / LL;
    int tid = threadIdx.x;
    for (int idx = tid; idx < 8*CC; idx += 256){
        int tok = idx >> 8, c = idx & 255;
        xf[tok*260 + c] = g_y[(t0+tok)*CC + c]*g_scale[c] + g_shift[c];
    }
    if (tid < 16){
        int tok = tid >> 1;
        float fi = (float)(t0 + tok - b*LL);
        float sL = sqrtf(160.f);
        float cv = (tid & 1) ? (fmodf(fi, sL) - 2.f)*0.5f : (fi/sL - 2.f)*0.5f;
        xf[tok*260 + 256 + (tid & 1)] = cv;
    }
    __syncthreads();
    int n = tid;
    float acc[8];
    #pragma unroll
    for (int i = 0; i < 8; i++) acc[i] = 0.f;
    #pragma unroll 2
    for (int k = 0; k < CP; k++){
        float w = g_W1T[k*256 + n];
        #pragma unroll
        for (int tok = 0; tok < 8; tok++) acc[tok] += xf[tok*260 + k]*w;
    }
    if (n < DM){
        #pragma unroll
        for (int tok = 0; tok < 8; tok++) g_u[(t0+tok)*DM + n] = acc[tok];
    } else {
        float hw = g_hw[b*DM + n - DM];
        #pragma unroll
        for (int tok = 0; tok < 8; tok++) g_v[(t0+tok)*DM + n - DM] = acc[tok] + hw;
    }
}

/* the big one: 128 pairs (8 l x 16 m) through 3 fused 128x128 layers.
   activations kept feature-major [d][p] so no transposes between layers. */
__global__ void __launch_bounds__(256,1) k_pairs(const float* __restrict__ b1,
                                                 const float* __restrict__ b2,
                                                 const float* __restrict__ b3,
                                                 const float* __restrict__ b4){
    extern __shared__ float sm[];
    float* Ws   = sm;                 /* 128*132, also temp u/v staging */
    float* actA = sm + 128*PAD;
    float* actB = sm + 2*128*PAD;
    float* u_s  = sm;                 /* [16][129] */
    float* v_s  = sm + 16*129;        /* [8][129]  */

    int m0 = blockIdx.x*16, l0 = blockIdx.y*8, b = blockIdx.z;
    int tid = threadIdx.x, tx = tid & 15, ty = tid >> 4;

    for (int idx = tid; idx < 16*DM; idx += 256){
        int mi = idx >> 7, d = idx & 127;
        u_s[mi*129 + d] = g_u[(b*LL + m0 + mi)*DM + d];
    }
    for (int idx = tid; idx < 8*DM; idx += 256){
        int li = idx >> 7, d = idx & 127;
        v_s[li*129 + d] = g_v[(b*LL + l0 + li)*DM + d];
    }
    __syncthreads();

    /* layer-1 activations: p = li*16 + mi */
    for (int idx = tid; idx < DM*128; idx += 256){
        int d = idx >> 7, p = idx & 127;
        int li = p >> 4, mi = p & 15;
        actA[d*PAD + p] = lrelu(v_s[li*129 + d] + u_s[mi*129 + d] + b1[d]);
    }

    float* src = actA;
    float* dst = actB;
    int d0 = ty*8, p0 = tx*8;

    #pragma unroll 1
    for (int layer = 0; layer < 3; layer++){
        const float* Wg = (layer == 0) ? g_W2T : (layer == 1) ? g_W3T : g_W4T;
        const float* bg = (layer == 0) ? b2   : (layer == 1) ? b3   : b4;
        __syncthreads();
        {   /* stage W k-major [k][d] with pad */
            const float4* s4 = (const float4*)Wg;
            #pragma unroll
            for (int q = 0; q < 16; q++){
                int idx = tid + q*256;
                int k = idx >> 5, dq = idx & 31;
                *(float4*)(Ws + k*PAD + dq*4) = s4[idx];
            }
        }
        __syncthreads();

        u64 acc[8][4];
        #pragma unroll
        for (int i = 0; i < 8; i++){
            float bv = bg[d0 + i];
            u64 bp = pk2(bv, bv);
            #pragma unroll
            for (int j = 0; j < 4; j++) acc[i][j] = bp;
        }
        #pragma unroll 4
        for (int k = 0; k < 128; k++){
            float4 a0 = *(const float4*)(Ws + k*PAD + d0);
            float4 a1 = *(const float4*)(Ws + k*PAD + d0 + 4);
            const u64* q2 = (const u64*)(src + k*PAD + p0);
            u64 v0 = q2[0], v1 = q2[1], v2 = q2[2], v3 = q2[3];
            float av[8] = {a0.x, a0.y, a0.z, a0.w, a1.x, a1.y, a1.z, a1.w};
            #pragma unroll
            for (int i = 0; i < 8; i++){
                u64 ap = pk2(av[i], av[i]);
                acc[i][0] = ffma2(ap, v0, acc[i][0]);
                acc[i][1] = ffma2(ap, v1, acc[i][1]);
                acc[i][2] = ffma2(ap, v2, acc[i][2]);
                acc[i][3] = ffma2(ap, v3, acc[i][3]);
            }
        }
        #pragma unroll
        for (int i = 0; i < 8; i++){
            float4 r0, r1;
            upk2(acc[i][0], r0.x, r0.y); upk2(acc[i][1], r0.z, r0.w);
            upk2(acc[i][2], r1.x, r1.y); upk2(acc[i][3], r1.z, r1.w);
            r0.x = lrelu(r0.x); r0.y = lrelu(r0.y); r0.z = lrelu(r0.z); r0.w = lrelu(r0.w);
            r1.x = lrelu(r1.x); r1.y = lrelu(r1.y); r1.z = lrelu(r1.z); r1.w = lrelu(r1.w);
            *(float4*)(dst + (d0+i)*PAD + p0)     = r0;
            *(float4*)(dst + (d0+i)*PAD + p0 + 4) = r1;
        }
        float* t = src; src = dst; dst = t;
    }
    __syncthreads();

    /* deterministic partial: sum over the 128 pairs for each feature d */
    if (tid < DM){
        float s = 0.f;
        #pragma unroll 8
        for (int p = 0; p < 128; p++) s += src[tid*PAD + p];
        g_part[(b*NT + blockIdx.y*10 + blockIdx.x)*DM + tid] = s;
    }
}

/* final reduction + 2-layer head */
__global__ void k_tail(const float* __restrict__ W5, const float* __restrict__ b5,
                       const float* __restrict__ W6, const float* __restrict__ b6,
                       float* __restrict__ out){
    __shared__ float s_s[DM], s5[DM];
    int b = blockIdx.x, tid = threadIdx.x;  /* 512 threads */
    if (tid < DM){
        float a = 0.f;
        for (int t = 0; t < NT; t++) a += g_part[(b*NT + t)*DM + tid];
        s_s[tid] = a;
    }
    __syncthreads();
    if (tid < DM){
        float a = 0.f;
        const float* w = W5 + tid*DM;
        #pragma unroll 8
        for (int k = 0; k < DM; k++) a += s_s[k]*w[k];
        s5[tid] = lrelu(a + b5[tid]);
    }
    __syncthreads();
    {
        float a = 0.f;
        const float* w = W6 + tid*DM;
        #pragma unroll 8
        for (int k = 0; k < DM; k++) a += s5[k]*w[k];
        out[b*DO + tid] = lrelu(a + b6[tid]);
    }
}

extern "C" void kernel_launch(void* const* d_in, const int* in_sizes, int n_in,
                              void* d_out, int out_size){
    const float* x      = (const float*)d_in[0];
    const float* h      = (const float*)d_in[1];
    const float* conv_w = (const float*)d_in[2];
    const float* conv_b = (const float*)d_in[3];
    const float* bn_g   = (const float*)d_in[4];
    const float* bn_b   = (const float*)d_in[5];
    const float* W1     = (const float*)d_in[6];
    const float* b1     = (const float*)d_in[7];
    const float* W2     = (const float*)d_in[8];
    const float* b2     = (const float*)d_in[9];
    const float* W3     = (const float*)d_in[10];
    const float* b3     = (const float*)d_in[11];
    const float* W4     = (const float*)d_in[12];
    const float* b4     = (const float*)d_in[13];
    const float* W5     = (const float*)d_in[14];
    const float* b5     = (const float*)d_in[15];
    const float* W6     = (const float*)d_in[16];
    const float* b6     = (const float*)d_in[17];
    float* out = (float*)d_out;

    cudaFuncSetAttribute(k_pairs, cudaFuncAttributeMaxDynamicSharedMemorySize,
                         3*128*PAD*(int)sizeof(float));

    k_prep<<<(KC*CC + 255)/256, 256>>>(conv_w, W1, W2, W3, W4);
    k_hw<<<BB, 128>>>(h, W1);
    k_conv<<<dim3(10, BB), 256>>>(x, conv_b);
    k_stats<<<CC, 256>>>(bn_g, bn_b);
    k_uv<<<TOK/8, 256>>>();
    k_pairs<<<dim3(10, 20, BB), 256, 3*128*PAD*sizeof(float)>>>(b1, b2, b3, b4);
    k_tail<<<BB, 512>>>(W5, b5, W6, b6, out);
}

// round 4
// speedup vs baseline: 2.2101x; 2.2101x over previous
#include <cuda_runtime.h>
#include <math.h>
#include <stdint.h>

#define LL 160
#define BB 16
#define EE 512
#define CC 256
#define HH 512
#define DM 128
#define DO 512
#define TOK (BB*LL)
#define CP 258
#define W1C 1028
#define KC (3*EE)
#define SPB 9
#define GRID_PAIRS (BB*SPB)   /* 144 */

__device__ float g_wT[KC*CC];
__device__ float g_W1T[CP*256];
__device__ float g_y[TOK*CC];
__device__ float g_scale[CC];
__device__ float g_shift[CC];
__device__ float g_u[TOK*DM];
__device__ float g_v[TOK*DM];
__device__ float g_hw[BB*DM];
__device__ float g_part[BB*SPB*DM];

__device__ __forceinline__ float lrelu(float x){ return x > 0.f ? x : 0.1f*x; }

__device__ __forceinline__ uint32_t f2tf32(float x){
    uint32_t r; asm("cvt.rna.tf32.f32 %0,%1;" : "=r"(r) : "f"(x)); return r;
}
__device__ __forceinline__ void mma_tf32(float& d0, float& d1, float& d2, float& d3,
                                         uint32_t a0, uint32_t a1, uint32_t a2, uint32_t a3,
                                         uint32_t b0, uint32_t b1){
    asm volatile("mma.sync.aligned.m16n8k8.row.col.f32.tf32.tf32.f32 "
                 "{%0,%1,%2,%3},{%4,%5,%6,%7},{%8,%9},{%0,%1,%2,%3};"
                 : "+f"(d0), "+f"(d1), "+f"(d2), "+f"(d3)
                 : "r"(a0), "r"(a1), "r"(a2), "r"(a3), "r"(b0), "r"(b1));
}

/* ---------------- prep / small kernels (passed in R2) ---------------- */
__global__ void k_prep(const float* __restrict__ conv_w, const float* __restrict__ W1){
    int idx = blockIdx.x*256 + threadIdx.x;
    if (idx < KC*CC){
        int kidx = idx >> 8, c = idx & 255;
        int e = kidx & 511, kk = kidx >> 9;
        g_wT[idx] = conv_w[c*KC + e*3 + kk];
    }
    if (idx < CP*256){
        int k = idx >> 8, n = idx & 255;
        g_W1T[idx] = (n < DM) ? W1[n*W1C + k] : W1[(n-DM)*W1C + CP + k];
    }
}

__global__ void k_hw(const float* __restrict__ h, const float* __restrict__ W1){
    __shared__ float hs[HH];
    int b = blockIdx.x, tid = threadIdx.x;
    for (int i = tid; i < HH; i += 128) hs[i] = h[b*HH + i];
    __syncthreads();
    float acc = 0.f;
    const float* w = W1 + tid*W1C + 2*CP;
    #pragma unroll 8
    for (int c = 0; c < HH; c++) acc += hs[c]*w[c];
    g_hw[b*DM + tid] = acc;
}

__global__ void __launch_bounds__(256,1) k_conv(const float* __restrict__ x,
                                                const float* __restrict__ conv_b){
    __shared__ float xs[18*512];
    __shared__ float ws[8*256];
    int l0 = blockIdx.x*16, b = blockIdx.y;
    int tid = threadIdx.x, tx = tid & 31, ty = tid >> 5;
    for (int idx = tid; idx < 18*512; idx += 256){
        int r = idx >> 9, e = idx & 511;
        int l = l0 + r - 1;
        xs[idx] = (l >= 0 && l < LL) ? x[(l*BB + b)*EE + e] : 0.f;
    }
    float acc[2][8];
    #pragma unroll
    for (int i = 0; i < 2; i++)
        #pragma unroll
        for (int j = 0; j < 8; j++) acc[i][j] = 0.f;

    for (int k0 = 0; k0 < KC; k0 += 8){
        __syncthreads();
        for (int idx = tid; idx < 8*256; idx += 256) ws[idx] = g_wT[k0*256 + idx];
        __syncthreads();
        #pragma unroll
        for (int kc = 0; kc < 8; kc++){
            int k = k0 + kc, e = k & 511, kk = k >> 9;
            float a0 = xs[(ty + kk)*512 + e];
            float a1 = xs[(ty + 8 + kk)*512 + e];
            const float* wr = ws + kc*256 + tx;
            #pragma unroll
            for (int j = 0; j < 8; j++){
                float wv = wr[32*j];
                acc[0][j] += a0*wv;
                acc[1][j] += a1*wv;
            }
        }
    }
    #pragma unroll
    for (int i = 0; i < 2; i++){
        int t = b*LL + l0 + ty + 8*i;
        #pragma unroll
        for (int j = 0; j < 8; j++){
            int c = tx + 32*j;
            g_y[t*CC + c] = lrelu(acc[i][j] + conv_b[c]);
        }
    }
}

__global__ void k_stats(const float* __restrict__ bn_g, const float* __restrict__ bn_b){
    __shared__ float s1[256], s2[256];
    int c = blockIdx.x, tid = threadIdx.x;
    float a = 0.f, q = 0.f;
    for (int t = tid; t < TOK; t += 256){
        float v = g_y[t*CC + c];
        a += v; q += v*v;
    }
    s1[tid] = a; s2[tid] = q; __syncthreads();
    for (int s = 128; s > 0; s >>= 1){
        if (tid < s){ s1[tid] += s1[tid+s]; s2[tid] += s2[tid+s]; }
        __syncthreads();
    }
    if (tid == 0){
        float mu = s1[0]/(float)TOK;
        float var = s2[0]/(float)TOK - mu*mu;
        float sc = bn_g[c]*rsqrtf(var + 1e-5f);
        g_scale[c] = sc;
        g_shift[c] = bn_b[c] - mu*sc;
    }
}

__global__ void __launch_bounds__(256,4) k_uv(){
    __shared__ float xf[8*260];
    int t0 = blockIdx.x*8;
    int b = t0 / LL;
    int tid = threadIdx.x;
    for (int idx = tid; idx < 8*CC; idx += 256){
        int tok = idx >> 8, c = idx & 255;
        xf[tok*260 + c] = g_y[(t0+tok)*CC + c]*g_scale[c] + g_shift[c];
    }
    if (tid < 16){
        int tok = tid >> 1;
        float fi = (float)(t0 + tok - b*LL);
        float sL = sqrtf(160.f);
        float cv = (tid & 1) ? (fmodf(fi, sL) - 2.f)*0.5f : (fi/sL - 2.f)*0.5f;
        xf[tok*260 + 256 + (tid & 1)] = cv;
    }
    __syncthreads();
    int n = tid;
    float acc[8];
    #pragma unroll
    for (int i = 0; i < 8; i++) acc[i] = 0.f;
    #pragma unroll 2
    for (int k = 0; k < CP; k++){
        float w = g_W1T[k*256 + n];
        #pragma unroll
        for (int tok = 0; tok < 8; tok++) acc[tok] += xf[tok*260 + k]*w;
    }
    if (n < DM){
        #pragma unroll
        for (int tok = 0; tok < 8; tok++) g_u[(t0+tok)*DM + n] = acc[tok];
    } else {
        float hw = g_hw[b*DM + n - DM];
        #pragma unroll
        for (int tok = 0; tok < 8; tok++) g_v[(t0+tok)*DM + n - DM] = acc[tok] + hw;
    }
}

/* ---------------- pair MLP on mma.sync tf32 ----------------
   persistent: 144 CTAs (9 per batch), 22-23 tiles each.
   warp = 16 pairs x 128 features; activations register-resident,
   layer-to-layer via in-warp fragment transpose (8 shfl / frag).
   smem float offsets:
     wfrag 0..49151, u_s 49152 (16x132), v_s 51264 (8x132),
     b1_s 52320 (128), bias_s 52448 (3x128), part_s 52832 (8x128) */
#define SM_WFRAG 0
#define SM_U     49152
#define SM_V     51264
#define SM_B1    52320
#define SM_BIAS  52448
#define SM_PART  52832
#define SM_TOTF  53856
#define DYN_SMEM (SM_TOTF*4)

__global__ void __launch_bounds__(256,1) k_pairs_mma(
        const float* __restrict__ W2, const float* __restrict__ W3, const float* __restrict__ W4,
        const float* __restrict__ b1, const float* __restrict__ b2,
        const float* __restrict__ b3, const float* __restrict__ b4){
    extern __shared__ float smf[];
    float* u_s    = smf + SM_U;
    float* v_s    = smf + SM_V;
    float* b1_s   = smf + SM_B1;
    float* bias_s = smf + SM_BIAS;
    float* part_s = smf + SM_PART;
    uint32_t* wfrag = (uint32_t*)(smf + SM_WFRAG);

    int tid = threadIdx.x, w = tid >> 5, t = tid & 31;
    int g = (t >> 2) & 7, c = t & 3;

    /* stage weights in B-fragment-major order, coalesced gmem reads */
    for (int l = 0; l < 3; l++){
        const float* W = (l == 0) ? W2 : (l == 1) ? W3 : W4;
        for (int idx = tid; idx < DM*DM; idx += 256){
            int n = idx >> 7, k = idx & 127;
            int kt = k >> 3, rr = (k >> 2) & 1;
            int lane = ((n & 7) << 2) | (k & 3);
            int off = l*16384 + kt*1024 + (n >> 3)*64 + lane*2 + rr;
            wfrag[off] = f2tf32(W[idx]);
        }
    }
    for (int i = tid; i < 128; i += 256){
        b1_s[i]          = b1[i];
        bias_s[i]        = b2[i];
        bias_s[128 + i]  = b3[i];
        bias_s[256 + i]  = b4[i];
    }

    int cta = blockIdx.x;
    int b = cta / SPB, s = cta % SPB;
    int t0 = s*22 + (s < 2 ? s : 2);
    int t1 = t0 + 22 + (s < 2 ? 1 : 0);

    uint32_t a[16][4];
    float    d[16][4];
    float    acc32[16][2];
    #pragma unroll
    for (int nt = 0; nt < 16; nt++){ acc32[nt][0] = 0.f; acc32[nt][1] = 0.f; }

    int srcA = (t & ~3) | ((t & 3) >> 1);
    int srcB = srcA + 2;
    bool par = (t & 1);

    for (int tt = t0; tt < t1; tt++){
        int lt0 = (tt / 10)*8, m0 = (tt % 10)*16;
        __syncthreads();
        for (int idx = tid; idx < 16*DM; idx += 256){
            int mi = idx >> 7, k = idx & 127;
            u_s[mi*132 + k] = g_u[(b*LL + m0 + mi)*DM + k];
        }
        for (int idx = tid; idx < 8*DM; idx += 256){
            int li = idx >> 7, k = idx & 127;
            v_s[li*132 + k] = g_v[(b*LL + lt0 + li)*DM + k];
        }
        __syncthreads();

        /* layer-1 activation fragments directly in registers */
        #pragma unroll
        for (int kt = 0; kt < 16; kt++){
            int k = kt*8 + c;
            float base0 = v_s[w*132 + k]     + b1_s[k];
            float base1 = v_s[w*132 + k + 4] + b1_s[k + 4];
            a[kt][0] = f2tf32(lrelu(u_s[g*132 + k]           + base0));
            a[kt][1] = f2tf32(lrelu(u_s[(g+8)*132 + k]       + base0));
            a[kt][2] = f2tf32(lrelu(u_s[g*132 + k + 4]       + base1));
            a[kt][3] = f2tf32(lrelu(u_s[(g+8)*132 + k + 4]   + base1));
        }

        #pragma unroll 1
        for (int l = 0; l < 3; l++){
            #pragma unroll
            for (int nt = 0; nt < 16; nt++){
                d[nt][0] = 0.f; d[nt][1] = 0.f; d[nt][2] = 0.f; d[nt][3] = 0.f;
            }
            const uint32_t* wl = wfrag + l*16384;
            #pragma unroll
            for (int kt = 0; kt < 16; kt++){
                const uint32_t* wk = wl + kt*1024 + t*2;
                #pragma unroll
                for (int nt = 0; nt < 16; nt++){
                    uint2 bb = *(const uint2*)(wk + nt*64);
                    mma_tf32(d[nt][0], d[nt][1], d[nt][2], d[nt][3],
                             a[kt][0], a[kt][1], a[kt][2], a[kt][3], bb.x, bb.y);
                }
            }
            if (l < 2){
                const float* bl = bias_s + l*128;
                #pragma unroll
                for (int nt = 0; nt < 16; nt++){
                    float bx = bl[nt*8 + 2*c], by = bl[nt*8 + 2*c + 1];
                    float e0 = lrelu(d[nt][0] + bx);
                    float e1 = lrelu(d[nt][1] + by);
                    float e2 = lrelu(d[nt][2] + bx);
                    float e3 = lrelu(d[nt][3] + by);
                    float s0A = __shfl_sync(0xffffffffu, e0, srcA);
                    float s1A = __shfl_sync(0xffffffffu, e1, srcA);
                    float s2A = __shfl_sync(0xffffffffu, e2, srcA);
                    float s3A = __shfl_sync(0xffffffffu, e3, srcA);
                    float s0B = __shfl_sync(0xffffffffu, e0, srcB);
                    float s1B = __shfl_sync(0xffffffffu, e1, srcB);
                    float s2B = __shfl_sync(0xffffffffu, e2, srcB);
                    float s3B = __shfl_sync(0xffffffffu, e3, srcB);
                    a[nt][0] = f2tf32(par ? s1A : s0A);
                    a[nt][1] = f2tf32(par ? s3A : s2A);
                    a[nt][2] = f2tf32(par ? s1B : s0B);
                    a[nt][3] = f2tf32(par ? s3B : s2B);
                }
            } else {
                const float* bl = bias_s + 256;
                #pragma unroll
                for (int nt = 0; nt < 16; nt++){
                    float bx = bl[nt*8 + 2*c], by = bl[nt*8 + 2*c + 1];
                    acc32[nt][0] += lrelu(d[nt][0] + bx) + lrelu(d[nt][2] + bx);
                    acc32[nt][1] += lrelu(d[nt][1] + by) + lrelu(d[nt][3] + by);
                }
            }
        }
    }

    /* reduce over the 8 row-groups (lanes stride 4) then across warps */
    #pragma unroll
    for (int nt = 0; nt < 16; nt++){
        #pragma unroll
        for (int r = 0; r < 2; r++){
            float v = acc32[nt][r];
            v += __shfl_xor_sync(0xffffffffu, v, 4);
            v += __shfl_xor_sync(0xffffffffu, v, 8);
            v += __shfl_xor_sync(0xffffffffu, v, 16);
            acc32[nt][r] = v;
        }
    }
    if (g == 0){
        #pragma unroll
        for (int nt = 0; nt < 16; nt++){
            part_s[w*128 + nt*8 + 2*c]     = acc32[nt][0];
            part_s[w*128 + nt*8 + 2*c + 1] = acc32[nt][1];
        }
    }
    __syncthreads();
    if (tid < 128){
        float r = 0.f;
        #pragma unroll
        for (int ww = 0; ww < 8; ww++) r += part_s[ww*128 + tid];
        g_part[(b*SPB + s)*DM + tid] = r;
    }
}

/* final reduction + 2-layer head */
__global__ void k_tail(const float* __restrict__ W5, const float* __restrict__ b5,
                       const float* __restrict__ W6, const float* __restrict__ b6,
                       float* __restrict__ out){
    __shared__ float s_s[DM], s5[DM];
    int b = blockIdx.x, tid = threadIdx.x;
    if (tid < DM){
        float a = 0.f;
        #pragma unroll
        for (int t = 0; t < SPB; t++) a += g_part[(b*SPB + t)*DM + tid];
        s_s[tid] = a;
    }
    __syncthreads();
    if (tid < DM){
        float a = 0.f;
        const float* w = W5 + tid*DM;
        #pragma unroll 8
        for (int k = 0; k < DM; k++) a += s_s[k]*w[k];
        s5[tid] = lrelu(a + b5[tid]);
    }
    __syncthreads();
    {
        float a = 0.f;
        const float* w = W6 + tid*DM;
        #pragma unroll 8
        for (int k = 0; k < DM; k++) a += s5[k]*w[k];
        out[b*DO + tid] = lrelu(a + b6[tid]);
    }
}

extern "C" void kernel_launch(void* const* d_in, const int* in_sizes, int n_in,
                              void* d_out, int out_size){
    const float* x      = (const float*)d_in[0];
    const float* h      = (const float*)d_in[1];
    const float* conv_w = (const float*)d_in[2];
    const float* conv_b = (const float*)d_in[3];
    const float* bn_g   = (const float*)d_in[4];
    const float* bn_b   = (const float*)d_in[5];
    const float* W1     = (const float*)d_in[6];
    const float* b1     = (const float*)d_in[7];
    const float* W2     = (const float*)d_in[8];
    const float* b2     = (const float*)d_in[9];
    const float* W3     = (const float*)d_in[10];
    const float* b3     = (const float*)d_in[11];
    const float* W4     = (const float*)d_in[12];
    const float* b4     = (const float*)d_in[13];
    const float* W5     = (const float*)d_in[14];
    const float* b5     = (const float*)d_in[15];
    const float* W6     = (const float*)d_in[16];
    const float* b6     = (const float*)d_in[17];
    float* out = (float*)d_out;

    cudaFuncSetAttribute(k_pairs_mma, cudaFuncAttributeMaxDynamicSharedMemorySize, DYN_SMEM);

    k_prep<<<(KC*CC + 255)/256, 256>>>(conv_w, W1);
    k_hw<<<BB, 128>>>(h, W1);
    k_conv<<<dim3(10, BB), 256>>>(x, conv_b);
    k_stats<<<CC, 256>>>(bn_g, bn_b);
    k_uv<<<TOK/8, 256>>>();
    k_pairs_mma<<<GRID_PAIRS, 256, DYN_SMEM>>>(W2, W3, W4, b1, b2, b3, b4);
    k_tail<<<BB, 512>>>(W5, b5, W6, b6, out);
}

// round 5
// speedup vs baseline: 2.7259x; 1.2334x over previous
#include <cuda_runtime.h>
#include <cuda_fp16.h>
#include <math.h>
#include <stdint.h>

#define LL 160
#define BB 16
#define EE 512
#define CC 256
#define HH 512
#define DM 128
#define DO 512
#define TOK (BB*LL)
#define CP 258
#define W1C 1028
#define KC (3*EE)
#define SPB 9
#define GRID_PAIRS (BB*SPB)   /* 144 */

__device__ float g_wT[KC*CC];
__device__ float g_W1T[CP*256];
__device__ float g_y[TOK*CC];
__device__ float g_scale[CC];
__device__ float g_shift[CC];
__device__ float g_u[TOK*DM];
__device__ float g_v[TOK*DM];
__device__ float g_hw[BB*DM];
__device__ float g_part[BB*SPB*DM];

__device__ __forceinline__ float lrelu(float x){ return x > 0.f ? x : 0.1f*x; }

__device__ __forceinline__ uint32_t h2pack(float lo, float hi){
    __half2 h = __floats2half2_rn(lo, hi);
    return *(uint32_t*)&h;
}
__device__ __forceinline__ void mma_f16(float& d0, float& d1, float& d2, float& d3,
                                        uint32_t a0, uint32_t a1, uint32_t a2, uint32_t a3,
                                        uint32_t b0, uint32_t b1){
    asm volatile("mma.sync.aligned.m16n8k16.row.col.f32.f16.f16.f32 "
                 "{%0,%1,%2,%3},{%4,%5,%6,%7},{%8,%9},{%0,%1,%2,%3};"
                 : "+f"(d0), "+f"(d1), "+f"(d2), "+f"(d3)
                 : "r"(a0), "r"(a1), "r"(a2), "r"(a3), "r"(b0), "r"(b1));
}

/* ---------------- prep / small kernels (known-good) ---------------- */
__global__ void k_prep(const float* __restrict__ conv_w, const float* __restrict__ W1){
    int idx = blockIdx.x*256 + threadIdx.x;
    if (idx < KC*CC){
        int kidx = idx >> 8, c = idx & 255;
        int e = kidx & 511, kk = kidx >> 9;
        g_wT[idx] = conv_w[c*KC + e*3 + kk];
    }
    if (idx < CP*256){
        int k = idx >> 8, n = idx & 255;
        g_W1T[idx] = (n < DM) ? W1[n*W1C + k] : W1[(n-DM)*W1C + CP + k];
    }
}

__global__ void k_hw(const float* __restrict__ h, const float* __restrict__ W1){
    __shared__ float hs[HH];
    int b = blockIdx.x, tid = threadIdx.x;
    for (int i = tid; i < HH; i += 128) hs[i] = h[b*HH + i];
    __syncthreads();
    float acc = 0.f;
    const float* w = W1 + tid*W1C + 2*CP;
    #pragma unroll 8
    for (int c = 0; c < HH; c++) acc += hs[c]*w[c];
    g_hw[b*DM + tid] = acc;
}

__global__ void __launch_bounds__(256,1) k_conv(const float* __restrict__ x,
                                                const float* __restrict__ conv_b){
    __shared__ float xs[18*512];
    __shared__ float ws[8*256];
    int l0 = blockIdx.x*16, b = blockIdx.y;
    int tid = threadIdx.x, tx = tid & 31, ty = tid >> 5;
    for (int idx = tid; idx < 18*512; idx += 256){
        int r = idx >> 9, e = idx & 511;
        int l = l0 + r - 1;
        xs[idx] = (l >= 0 && l < LL) ? x[(l*BB + b)*EE + e] : 0.f;
    }
    float acc[2][8];
    #pragma unroll
    for (int i = 0; i < 2; i++)
        #pragma unroll
        for (int j = 0; j < 8; j++) acc[i][j] = 0.f;

    for (int k0 = 0; k0 < KC; k0 += 8){
        __syncthreads();
        for (int idx = tid; idx < 8*256; idx += 256) ws[idx] = g_wT[k0*256 + idx];
        __syncthreads();
        #pragma unroll
        for (int kc = 0; kc < 8; kc++){
            int k = k0 + kc, e = k & 511, kk = k >> 9;
            float a0 = xs[(ty + kk)*512 + e];
            float a1 = xs[(ty + 8 + kk)*512 + e];
            const float* wr = ws + kc*256 + tx;
            #pragma unroll
            for (int j = 0; j < 8; j++){
                float wv = wr[32*j];
                acc[0][j] += a0*wv;
                acc[1][j] += a1*wv;
            }
        }
    }
    #pragma unroll
    for (int i = 0; i < 2; i++){
        int t = b*LL + l0 + ty + 8*i;
        #pragma unroll
        for (int j = 0; j < 8; j++){
            int c = tx + 32*j;
            g_y[t*CC + c] = lrelu(acc[i][j] + conv_b[c]);
        }
    }
}

__global__ void k_stats(const float* __restrict__ bn_g, const float* __restrict__ bn_b){
    __shared__ float s1[256], s2[256];
    int c = blockIdx.x, tid = threadIdx.x;
    float a = 0.f, q = 0.f;
    for (int t = tid; t < TOK; t += 256){
        float v = g_y[t*CC + c];
        a += v; q += v*v;
    }
    s1[tid] = a; s2[tid] = q; __syncthreads();
    for (int s = 128; s > 0; s >>= 1){
        if (tid < s){ s1[tid] += s1[tid+s]; s2[tid] += s2[tid+s]; }
        __syncthreads();
    }
    if (tid == 0){
        float mu = s1[0]/(float)TOK;
        float var = s2[0]/(float)TOK - mu*mu;
        float sc = bn_g[c]*rsqrtf(var + 1e-5f);
        g_scale[c] = sc;
        g_shift[c] = bn_b[c] - mu*sc;
    }
}

__global__ void __launch_bounds__(256,4) k_uv(){
    __shared__ float xf[8*260];
    int t0 = blockIdx.x*8;
    int b = t0 / LL;
    int tid = threadIdx.x;
    for (int idx = tid; idx < 8*CC; idx += 256){
        int tok = idx >> 8, c = idx & 255;
        xf[tok*260 + c] = g_y[(t0+tok)*CC + c]*g_scale[c] + g_shift[c];
    }
    if (tid < 16){
        int tok = tid >> 1;
        float fi = (float)(t0 + tok - b*LL);
        float sL = sqrtf(160.f);
        float cv = (tid & 1) ? (fmodf(fi, sL) - 2.f)*0.5f : (fi/sL - 2.f)*0.5f;
        xf[tok*260 + 256 + (tid & 1)] = cv;
    }
    __syncthreads();
    int n = tid;
    float acc[8];
    #pragma unroll
    for (int i = 0; i < 8; i++) acc[i] = 0.f;
    #pragma unroll 2
    for (int k = 0; k < CP; k++){
        float w = g_W1T[k*256 + n];
        #pragma unroll
        for (int tok = 0; tok < 8; tok++) acc[tok] += xf[tok*260 + k]*w;
    }
    if (n < DM){
        #pragma unroll
        for (int tok = 0; tok < 8; tok++) g_u[(t0+tok)*DM + n] = acc[tok];
    } else {
        float hw = g_hw[b*DM + n - DM];
        #pragma unroll
        for (int tok = 0; tok < 8; tok++) g_v[(t0+tok)*DM + n - DM] = acc[tok] + hw;
    }
}

/* ---------------- pair MLP on mma.sync m16n8k16 fp16 ----------------
   persistent: 144 CTAs (9 per batch), 22-23 tiles of 128 pairs each.
   warp = 16 pairs x 128 features, register-resident activations;
   fp16 k16 layout makes the D->A inter-layer transpose shuffle-free.
   smem (floats): wfrag 24576 (=3*4096 uint2), u 16x132, v 8x132,
                  b1 128, bias 3*128, part 8*128                        */
#define SM_U     24576
#define SM_V     (SM_U + 16*132)
#define SM_B1    (SM_V + 8*132)
#define SM_BIAS  (SM_B1 + 128)
#define SM_PART  (SM_BIAS + 384)
#define SM_TOTF  (SM_PART + 1024)
#define DYN_SMEM (SM_TOTF*4)

__global__ void __launch_bounds__(256,1) k_pairs_mma(
        const float* __restrict__ W2, const float* __restrict__ W3, const float* __restrict__ W4,
        const float* __restrict__ b1, const float* __restrict__ b2,
        const float* __restrict__ b3, const float* __restrict__ b4){
    extern __shared__ float smf[];
    float* u_s    = smf + SM_U;
    float* v_s    = smf + SM_V;
    float* b1_s   = smf + SM_B1;
    float* bias_s = smf + SM_BIAS;
    float* part_s = smf + SM_PART;
    uint2* wfrag  = (uint2*)smf;   /* [l][kt 8][nt 16][lane 32] */

    int tid = threadIdx.x, w = tid >> 5, t = tid & 31;
    int g = t >> 2, c = t & 3;

    /* stage weights as B fragments: b0 = half2(W[n][k0],W[n][k0+1]),
       b1 = half2(W[n][k0+8],W[n][k0+9]); n = nt*8+g, k0 = kt*16+2c */
    for (int l = 0; l < 3; l++){
        const float* W = (l == 0) ? W2 : (l == 1) ? W3 : W4;
        for (int idx = tid; idx < 4096; idx += 256){
            int lane = idx & 31, nt = (idx >> 5) & 15, kt = idx >> 9;
            int gg = lane >> 2, cc = lane & 3;
            const float* Wr = W + (nt*8 + gg)*DM + kt*16 + 2*cc;
            uint2 fr;
            fr.x = h2pack(Wr[0], Wr[1]);
            fr.y = h2pack(Wr[8], Wr[9]);
            wfrag[l*4096 + idx] = fr;
        }
    }
    for (int i = tid; i < 128; i += 256){
        b1_s[i]          = b1[i];
        bias_s[i]        = b2[i];
        bias_s[128 + i]  = b3[i];
        bias_s[256 + i]  = b4[i];
    }

    int cta = blockIdx.x;
    int b = cta / SPB, s = cta % SPB;
    int t0 = s*22 + (s < 2 ? s : 2);
    int t1 = t0 + 22 + (s < 2 ? 1 : 0);

    uint32_t a[8][4];
    float    d[16][4];
    float    acc32[16][2];
    #pragma unroll
    for (int nt = 0; nt < 16; nt++){ acc32[nt][0] = 0.f; acc32[nt][1] = 0.f; }

    for (int tt = t0; tt < t1; tt++){
        int lt0 = (tt / 10)*8, m0 = (tt % 10)*16;
        __syncthreads();
        for (int idx = tid; idx < 16*DM; idx += 256){
            int mi = idx >> 7, k = idx & 127;
            u_s[mi*132 + k] = g_u[(b*LL + m0 + mi)*DM + k];
        }
        for (int idx = tid; idx < 8*DM; idx += 256){
            int li = idx >> 7, k = idx & 127;
            v_s[li*132 + k] = g_v[(b*LL + lt0 + li)*DM + k];
        }
        __syncthreads();

        /* layer-1 activation fragments (warp w = pairs (li=w, mi=0..15)) */
        #pragma unroll
        for (int kt = 0; kt < 8; kt++){
            int k = kt*16 + 2*c;
            const float* vr = v_s + w*132 + k;
            const float* br = b1_s + k;
            float vb0 = vr[0] + br[0], vb1 = vr[1] + br[1];
            float vb8 = vr[8] + br[8], vb9 = vr[9] + br[9];
            const float* ug  = u_s + g*132 + k;
            const float* uh  = u_s + (g+8)*132 + k;
            a[kt][0] = h2pack(lrelu(ug[0] + vb0), lrelu(ug[1] + vb1));
            a[kt][1] = h2pack(lrelu(uh[0] + vb0), lrelu(uh[1] + vb1));
            a[kt][2] = h2pack(lrelu(ug[8] + vb8), lrelu(ug[9] + vb9));
            a[kt][3] = h2pack(lrelu(uh[8] + vb8), lrelu(uh[9] + vb9));
        }

        #pragma unroll 1
        for (int l = 0; l < 3; l++){
            #pragma unroll
            for (int nt = 0; nt < 16; nt++){
                d[nt][0] = 0.f; d[nt][1] = 0.f; d[nt][2] = 0.f; d[nt][3] = 0.f;
            }
            const uint2* wl = wfrag + l*4096 + t;
            #pragma unroll
            for (int kt = 0; kt < 8; kt++){
                const uint2* wk = wl + kt*512;
                #pragma unroll
                for (int nt = 0; nt < 16; nt++){
                    uint2 bb = wk[nt*32];
                    mma_f16(d[nt][0], d[nt][1], d[nt][2], d[nt][3],
                            a[kt][0], a[kt][1], a[kt][2], a[kt][3], bb.x, bb.y);
                }
            }
            if (l < 2){
                const float* bl = bias_s + l*128;
                #pragma unroll
                for (int kt = 0; kt < 8; kt++){
                    float bx0 = bl[kt*16 + 2*c],     by0 = bl[kt*16 + 2*c + 1];
                    float bx8 = bl[kt*16 + 2*c + 8], by8 = bl[kt*16 + 2*c + 9];
                    a[kt][0] = h2pack(lrelu(d[2*kt][0]   + bx0), lrelu(d[2*kt][1]   + by0));
                    a[kt][1] = h2pack(lrelu(d[2*kt][2]   + bx0), lrelu(d[2*kt][3]   + by0));
                    a[kt][2] = h2pack(lrelu(d[2*kt+1][0] + bx8), lrelu(d[2*kt+1][1] + by8));
                    a[kt][3] = h2pack(lrelu(d[2*kt+1][2] + bx8), lrelu(d[2*kt+1][3] + by8));
                }
            } else {
                const float* bl = bias_s + 256;
                #pragma unroll
                for (int nt = 0; nt < 16; nt++){
                    float bx = bl[nt*8 + 2*c], by = bl[nt*8 + 2*c + 1];
                    acc32[nt][0] += lrelu(d[nt][0] + bx) + lrelu(d[nt][2] + bx);
                    acc32[nt][1] += lrelu(d[nt][1] + by) + lrelu(d[nt][3] + by);
                }
            }
        }
    }

    /* reduce over 8 row-groups (lane stride 4), then across warps */
    #pragma unroll
    for (int nt = 0; nt < 16; nt++){
        #pragma unroll
        for (int r = 0; r < 2; r++){
            float v = acc32[nt][r];
            v += __shfl_xor_sync(0xffffffffu, v, 4);
            v += __shfl_xor_sync(0xffffffffu, v, 8);
            v += __shfl_xor_sync(0xffffffffu, v, 16);
            acc32[nt][r] = v;
        }
    }
    if (g == 0){
        #pragma unroll
        for (int nt = 0; nt < 16; nt++){
            part_s[w*128 + nt*8 + 2*c]     = acc32[nt][0];
            part_s[w*128 + nt*8 + 2*c + 1] = acc32[nt][1];
        }
    }
    __syncthreads();
    if (tid < 128){
        float r = 0.f;
        #pragma unroll
        for (int ww = 0; ww < 8; ww++) r += part_s[ww*128 + tid];
        g_part[(b*SPB + s)*DM + tid] = r;
    }
}

/* final reduction + 2-layer head */
__global__ void k_tail(const float* __restrict__ W5, const float* __restrict__ b5,
                       const float* __restrict__ W6, const float* __restrict__ b6,
                       float* __restrict__ out){
    __shared__ float s_s[DM], s5[DM];
    int b = blockIdx.x, tid = threadIdx.x;
    if (tid < DM){
        float a = 0.f;
        #pragma unroll
        for (int t = 0; t < SPB; t++) a += g_part[(b*SPB + t)*DM + tid];
        s_s[tid] = a;
    }
    __syncthreads();
    if (tid < DM){
        float a = 0.f;
        const float* w = W5 + tid*DM;
        #pragma unroll 8
        for (int k = 0; k < DM; k++) a += s_s[k]*w[k];
        s5[tid] = lrelu(a + b5[tid]);
    }
    __syncthreads();
    {
        float a = 0.f;
        const float* w = W6 + tid*DM;
        #pragma unroll 8
        for (int k = 0; k < DM; k++) a += s5[k]*w[k];
        out[b*DO + tid] = lrelu(a + b6[tid]);
    }
}

extern "C" void kernel_launch(void* const* d_in, const int* in_sizes, int n_in,
                              void* d_out, int out_size){
    const float* x      = (const float*)d_in[0];
    const float* h      = (const float*)d_in[1];
    const float* conv_w = (const float*)d_in[2];
    const float* conv_b = (const float*)d_in[3];
    const float* bn_g   = (const float*)d_in[4];
    const float* bn_b   = (const float*)d_in[5];
    const float* W1     = (const float*)d_in[6];
    const float* b1     = (const float*)d_in[7];
    const float* W2     = (const float*)d_in[8];
    const float* b2     = (const float*)d_in[9];
    const float* W3     = (const float*)d_in[10];
    const float* b3     = (const float*)d_in[11];
    const float* W4     = (const float*)d_in[12];
    const float* b4     = (const float*)d_in[13];
    const float* W5     = (const float*)d_in[14];
    const float* b5     = (const float*)d_in[15];
    const float* W6     = (const float*)d_in[16];
    const float* b6     = (const float*)d_in[17];
    float* out = (float*)d_out;

    cudaFuncSetAttribute(k_pairs_mma, cudaFuncAttributeMaxDynamicSharedMemorySize, DYN_SMEM);

    k_prep<<<(KC*CC + 255)/256, 256>>>(conv_w, W1);
    k_hw<<<BB, 128>>>(h, W1);
    k_conv<<<dim3(10, BB), 256>>>(x, conv_b);
    k_stats<<<CC, 256>>>(bn_g, bn_b);
    k_uv<<<TOK/8, 256>>>();
    k_pairs_mma<<<GRID_PAIRS, 256, DYN_SMEM>>>(W2, W3, W4, b1, b2, b3, b4);
    k_tail<<<BB, 512>>>(W5, b5, W6, b6, out);
}

// round 6
// speedup vs baseline: 4.2690x; 1.5661x over previous
#include <cuda_runtime.h>
#include <cuda_fp16.h>
#include <math.h>
#include <stdint.h>

#define LL 160
#define BB 16
#define EE 512
#define CC 256
#define HH 512
#define DM 128
#define DO 512
#define TOK (BB*LL)
#define CP 258
#define W1C 1028
#define KC (3*EE)            /* 1536 */
#define SPB 9
#define GRID_PAIRS (BB*SPB)  /* 144 */
#define NKT (KC/16)          /* 96 global kt for conv */

__device__ __half g_whfrag[NKT*32*32*4];  /* conv W fp16 B-fragments [kt][nt][lane][4] */
__device__ float g_W1T[CP*256];
__device__ float g_y[TOK*CC];
__device__ float g_ssum[20*256];
__device__ float g_ssq[20*256];
__device__ float g_scale[CC];
__device__ float g_shift[CC];
__device__ float g_u[TOK*DM];
__device__ float g_v[TOK*DM];
__device__ float g_hw[BB*DM];
__device__ float g_part[BB*SPB*DM];

__device__ __forceinline__ float lrelu(float x){ return x > 0.f ? x : 0.1f*x; }

__device__ __forceinline__ uint32_t h2pack(float lo, float hi){
    __half2 h = __floats2half2_rn(lo, hi);
    return *(uint32_t*)&h;
}
__device__ __forceinline__ void mma_f16(float& d0, float& d1, float& d2, float& d3,
                                        uint32_t a0, uint32_t a1, uint32_t a2, uint32_t a3,
                                        uint32_t b0, uint32_t b1){
    asm volatile("mma.sync.aligned.m16n8k16.row.col.f32.f16.f16.f32 "
                 "{%0,%1,%2,%3},{%4,%5,%6,%7},{%8,%9},{%0,%1,%2,%3};"
                 : "+f"(d0), "+f"(d1), "+f"(d2), "+f"(d3)
                 : "r"(a0), "r"(a1), "r"(a2), "r"(a3), "r"(b0), "r"(b1));
}

/* ---------------- prep: conv weights to fp16 fragments + W1 transpose -------- */
__global__ void k_prep(const float* __restrict__ conv_w, const float* __restrict__ W1){
    int idx = blockIdx.x*256 + threadIdx.x;
    if (idx < KC*CC){
        int k = idx >> 8, n = idx & 255;      /* k = kk*512 + e */
        int e = k & 511, kk = k >> 9;
        float v = conv_w[n*KC + e*3 + kk];
        int kt = k >> 4, r = k & 15;
        int nt = n >> 3, gg = n & 7, c = (r & 7) >> 1;
        int lane = gg*4 + c;
        int hs = ((r >> 3) << 1) | (r & 1);
        g_whfrag[(((kt*32 + nt)*32 + lane) << 2) + hs] = __float2half(v);
    }
    if (idx < CP*256){
        int k = idx >> 8, n = idx & 255;
        g_W1T[idx] = (n < DM) ? W1[n*W1C + k] : W1[(n-DM)*W1C + CP + k];
    }
}

__global__ void k_hw(const float* __restrict__ h, const float* __restrict__ W1){
    __shared__ float hs[HH];
    int b = blockIdx.x, tid = threadIdx.x;
    for (int i = tid; i < HH; i += 128) hs[i] = h[b*HH + i];
    __syncthreads();
    float acc = 0.f;
    const float* w = W1 + tid*W1C + 2*CP;
    #pragma unroll 8
    for (int c = 0; c < HH; c++) acc += hs[c]*w[c];
    g_hw[b*DM + tid] = acc;
}

/* ---------------- conv1d as fp16 mma GEMM ----------------
   block = 16 tokens x 256 channels; K=1536 in 32 chunks of 48.
   xh32: [18 rows][260 u32] half2, stride 260 -> conflict-free A loads.
   wfr:  [3 kt][32 nt][32 lane] uint2 B fragments, coalesced staging. */
__global__ void __launch_bounds__(256,1) k_conv(const float* __restrict__ x,
                                                const float* __restrict__ conv_b){
    __shared__ uint32_t xh32[18*260];
    __shared__ uint2 wfr[3*32*32];
    int l0 = blockIdx.x*16, b = blockIdx.y;
    int tid = threadIdx.x, w = tid >> 5, t = tid & 31;
    int g = t >> 2, c = t & 3;

    for (int idx = tid; idx < 18*256; idx += 256){
        int r = idx >> 8, i = idx & 255;
        int l = l0 + r - 1;
        uint32_t pv = 0u;
        if (l >= 0 && l < LL){
            const float2 xv = *(const float2*)(x + (l*BB + b)*EE + 2*i);
            pv = h2pack(xv.x, xv.y);
        }
        xh32[r*260 + i] = pv;
    }

    float d[4][4];
    #pragma unroll
    for (int j = 0; j < 4; j++){ d[j][0]=0.f; d[j][1]=0.f; d[j][2]=0.f; d[j][3]=0.f; }

    const uint2* gsrc = (const uint2*)g_whfrag;
    for (int cc = 0; cc < 32; cc++){
        __syncthreads();
        const uint2* src = gsrc + cc*3072;
        #pragma unroll
        for (int q = 0; q < 12; q++) wfr[tid + q*256] = src[tid + q*256];
        __syncthreads();
        #pragma unroll
        for (int kt = 0; kt < 3; kt++){
            int k = cc*48 + kt*16;
            int kk = k >> 9, e2 = (k & 511) >> 1;
            const uint32_t* r0 = xh32 + (g + kk)*260 + e2 + c;
            const uint32_t* r1 = xh32 + (g + 8 + kk)*260 + e2 + c;
            uint32_t a0 = r0[0], a1 = r1[0], a2 = r0[4], a3 = r1[4];
            const uint2* wk = wfr + (kt*32 + w*4)*32 + t;
            #pragma unroll
            for (int j = 0; j < 4; j++){
                uint2 bb = wk[j*32];
                mma_f16(d[j][0], d[j][1], d[j][2], d[j][3], a0, a1, a2, a3, bb.x, bb.y);
            }
        }
    }
    #pragma unroll
    for (int j = 0; j < 4; j++){
        int n = w*32 + j*8 + 2*c;
        float bx = conv_b[n], by = conv_b[n+1];
        int trow = (b*LL + l0 + g)*CC;
        g_y[trow + n]             = lrelu(d[j][0] + bx);
        g_y[trow + n + 1]         = lrelu(d[j][1] + by);
        g_y[trow + 8*CC + n]      = lrelu(d[j][2] + bx);
        g_y[trow + 8*CC + n + 1]  = lrelu(d[j][3] + by);
    }
}

/* BN stats: coalesced partial pass + tiny finalize */
__global__ void k_stats_part(){
    int blk = blockIdx.x, tid = threadIdx.x;   /* 20 blocks, 256 thr */
    int t0 = blk*128;
    float a = 0.f, q = 0.f;
    for (int tt = 0; tt < 128; tt++){
        float v = g_y[(t0 + tt)*CC + tid];
        a += v; q += v*v;
    }
    g_ssum[blk*256 + tid] = a;
    g_ssq[blk*256 + tid]  = q;
}
__global__ void k_stats_fin(const float* __restrict__ bn_g, const float* __restrict__ bn_b){
    int c = threadIdx.x;   /* 256 thr */
    float a = 0.f, q = 0.f;
    #pragma unroll
    for (int blk = 0; blk < 20; blk++){
        a += g_ssum[blk*256 + c];
        q += g_ssq[blk*256 + c];
    }
    float mu = a/(float)TOK;
    float var = q/(float)TOK - mu*mu;
    float sc = bn_g[c]*rsqrtf(var + 1e-5f);
    g_scale[c] = sc;
    g_shift[c] = bn_b[c] - mu*sc;
}

__global__ void __launch_bounds__(256,4) k_uv(){
    __shared__ float xf[8*260];
    int t0 = blockIdx.x*8;
    int b = t0 / LL;
    int tid = threadIdx.x;
    for (int idx = tid; idx < 8*CC; idx += 256){
        int tok = idx >> 8, c = idx & 255;
        xf[tok*260 + c] = g_y[(t0+tok)*CC + c]*g_scale[c] + g_shift[c];
    }
    if (tid < 16){
        int tok = tid >> 1;
        float fi = (float)(t0 + tok - b*LL);
        float sL = sqrtf(160.f);
        float cv = (tid & 1) ? (fmodf(fi, sL) - 2.f)*0.5f : (fi/sL - 2.f)*0.5f;
        xf[tok*260 + 256 + (tid & 1)] = cv;
    }
    __syncthreads();
    int n = tid;
    float acc[8];
    #pragma unroll
    for (int i = 0; i < 8; i++) acc[i] = 0.f;
    #pragma unroll 2
    for (int k = 0; k < CP; k++){
        float w = g_W1T[k*256 + n];
        #pragma unroll
        for (int tok = 0; tok < 8; tok++) acc[tok] += xf[tok*260 + k]*w;
    }
    if (n < DM){
        #pragma unroll
        for (int tok = 0; tok < 8; tok++) g_u[(t0+tok)*DM + n] = acc[tok];
    } else {
        float hw = g_hw[b*DM + n - DM];
        #pragma unroll
        for (int tok = 0; tok < 8; tok++) g_v[(t0+tok)*DM + n - DM] = acc[tok] + hw;
    }
}

/* ---------------- pair MLP on mma.sync m16n8k16 fp16 (unchanged, known-good) */
#define SM_U     24576
#define SM_V     (SM_U + 16*132)
#define SM_B1    (SM_V + 8*132)
#define SM_BIAS  (SM_B1 + 128)
#define SM_PART  (SM_BIAS + 384)
#define SM_TOTF  (SM_PART + 1024)
#define DYN_SMEM (SM_TOTF*4)

__global__ void __launch_bounds__(256,1) k_pairs_mma(
        const float* __restrict__ W2, const float* __restrict__ W3, const float* __restrict__ W4,
        const float* __restrict__ b1, const float* __restrict__ b2,
        const float* __restrict__ b3, const float* __restrict__ b4){
    extern __shared__ float smf[];
    float* u_s    = smf + SM_U;
    float* v_s    = smf + SM_V;
    float* b1_s   = smf + SM_B1;
    float* bias_s = smf + SM_BIAS;
    float* part_s = smf + SM_PART;
    uint2* wfrag  = (uint2*)smf;

    int tid = threadIdx.x, w = tid >> 5, t = tid & 31;
    int g = t >> 2, c = t & 3;

    for (int l = 0; l < 3; l++){
        const float* W = (l == 0) ? W2 : (l == 1) ? W3 : W4;
        for (int idx = tid; idx < 4096; idx += 256){
            int lane = idx & 31, nt = (idx >> 5) & 15, kt = idx >> 9;
            int gg = lane >> 2, cc = lane & 3;
            const float* Wr = W + (nt*8 + gg)*DM + kt*16 + 2*cc;
            uint2 fr;
            fr.x = h2pack(Wr[0], Wr[1]);
            fr.y = h2pack(Wr[8], Wr[9]);
            wfrag[l*4096 + idx] = fr;
        }
    }
    for (int i = tid; i < 128; i += 256){
        b1_s[i]          = b1[i];
        bias_s[i]        = b2[i];
        bias_s[128 + i]  = b3[i];
        bias_s[256 + i]  = b4[i];
    }

    int cta = blockIdx.x;
    int b = cta / SPB, s = cta % SPB;
    int t0 = s*22 + (s < 2 ? s : 2);
    int t1 = t0 + 22 + (s < 2 ? 1 : 0);

    uint32_t a[8][4];
    float    d[16][4];
    float    acc32[16][2];
    #pragma unroll
    for (int nt = 0; nt < 16; nt++){ acc32[nt][0] = 0.f; acc32[nt][1] = 0.f; }

    for (int tt = t0; tt < t1; tt++){
        int lt0 = (tt / 10)*8, m0 = (tt % 10)*16;
        __syncthreads();
        for (int idx = tid; idx < 16*DM; idx += 256){
            int mi = idx >> 7, k = idx & 127;
            u_s[mi*132 + k] = g_u[(b*LL + m0 + mi)*DM + k];
        }
        for (int idx = tid; idx < 8*DM; idx += 256){
            int li = idx >> 7, k = idx & 127;
            v_s[li*132 + k] = g_v[(b*LL + lt0 + li)*DM + k];
        }
        __syncthreads();

        #pragma unroll
        for (int kt = 0; kt < 8; kt++){
            int k = kt*16 + 2*c;
            const float* vr = v_s + w*132 + k;
            const float* br = b1_s + k;
            float vb0 = vr[0] + br[0], vb1 = vr[1] + br[1];
            float vb8 = vr[8] + br[8], vb9 = vr[9] + br[9];
            const float* ug  = u_s + g*132 + k;
            const float* uh  = u_s + (g+8)*132 + k;
            a[kt][0] = h2pack(lrelu(ug[0] + vb0), lrelu(ug[1] + vb1));
            a[kt][1] = h2pack(lrelu(uh[0] + vb0), lrelu(uh[1] + vb1));
            a[kt][2] = h2pack(lrelu(ug[8] + vb8), lrelu(ug[9] + vb9));
            a[kt][3] = h2pack(lrelu(uh[8] + vb8), lrelu(uh[9] + vb9));
        }

        #pragma unroll 1
        for (int l = 0; l < 3; l++){
            #pragma unroll
            for (int nt = 0; nt < 16; nt++){
                d[nt][0] = 0.f; d[nt][1] = 0.f; d[nt][2] = 0.f; d[nt][3] = 0.f;
            }
            const uint2* wl = wfrag + l*4096 + t;
            #pragma unroll
            for (int kt = 0; kt < 8; kt++){
                const uint2* wk = wl + kt*512;
                #pragma unroll
                for (int nt = 0; nt < 16; nt++){
                    uint2 bb = wk[nt*32];
                    mma_f16(d[nt][0], d[nt][1], d[nt][2], d[nt][3],
                            a[kt][0], a[kt][1], a[kt][2], a[kt][3], bb.x, bb.y);
                }
            }
            if (l < 2){
                const float* bl = bias_s + l*128;
                #pragma unroll
                for (int kt = 0; kt < 8; kt++){
                    float bx0 = bl[kt*16 + 2*c],     by0 = bl[kt*16 + 2*c + 1];
                    float bx8 = bl[kt*16 + 2*c + 8], by8 = bl[kt*16 + 2*c + 9];
                    a[kt][0] = h2pack(lrelu(d[2*kt][0]   + bx0), lrelu(d[2*kt][1]   + by0));
                    a[kt][1] = h2pack(lrelu(d[2*kt][2]   + bx0), lrelu(d[2*kt][3]   + by0));
                    a[kt][2] = h2pack(lrelu(d[2*kt+1][0] + bx8), lrelu(d[2*kt+1][1] + by8));
                    a[kt][3] = h2pack(lrelu(d[2*kt+1][2] + bx8), lrelu(d[2*kt+1][3] + by8));
                }
            } else {
                const float* bl = bias_s + 256;
                #pragma unroll
                for (int nt = 0; nt < 16; nt++){
                    float bx = bl[nt*8 + 2*c], by = bl[nt*8 + 2*c + 1];
                    acc32[nt][0] += lrelu(d[nt][0] + bx) + lrelu(d[nt][2] + bx);
                    acc32[nt][1] += lrelu(d[nt][1] + by) + lrelu(d[nt][3] + by);
                }
            }
        }
    }

    #pragma unroll
    for (int nt = 0; nt < 16; nt++){
        #pragma unroll
        for (int r = 0; r < 2; r++){
            float v = acc32[nt][r];
            v += __shfl_xor_sync(0xffffffffu, v, 4);
            v += __shfl_xor_sync(0xffffffffu, v, 8);
            v += __shfl_xor_sync(0xffffffffu, v, 16);
            acc32[nt][r] = v;
        }
    }
    if (g == 0){
        #pragma unroll
        for (int nt = 0; nt < 16; nt++){
            part_s[w*128 + nt*8 + 2*c]     = acc32[nt][0];
            part_s[w*128 + nt*8 + 2*c + 1] = acc32[nt][1];
        }
    }
    __syncthreads();
    if (tid < 128){
        float r = 0.f;
        #pragma unroll
        for (int ww = 0; ww < 8; ww++) r += part_s[ww*128 + tid];
        g_part[(b*SPB + s)*DM + tid] = r;
    }
}

/* final reduction + 2-layer head */
__global__ void k_tail(const float* __restrict__ W5, const float* __restrict__ b5,
                       const float* __restrict__ W6, const float* __restrict__ b6,
                       float* __restrict__ out){
    __shared__ float s_s[DM], s5[DM];
    int b = blockIdx.x, tid = threadIdx.x;
    if (tid < DM){
        float a = 0.f;
        #pragma unroll
        for (int t = 0; t < SPB; t++) a += g_part[(b*SPB + t)*DM + tid];
        s_s[tid] = a;
    }
    __syncthreads();
    if (tid < DM){
        float a = 0.f;
        const float* w = W5 + tid*DM;
        #pragma unroll 8
        for (int k = 0; k < DM; k++) a += s_s[k]*w[k];
        s5[tid] = lrelu(a + b5[tid]);
    }
    __syncthreads();
    {
        float a = 0.f;
        const float* w = W6 + tid*DM;
        #pragma unroll 8
        for (int k = 0; k < DM; k++) a += s5[k]*w[k];
        out[b*DO + tid] = lrelu(a + b6[tid]);
    }
}

extern "C" void kernel_launch(void* const* d_in, const int* in_sizes, int n_in,
                              void* d_out, int out_size){
    const float* x      = (const float*)d_in[0];
    const float* h      = (const float*)d_in[1];
    const float* conv_w = (const float*)d_in[2];
    const float* conv_b = (const float*)d_in[3];
    const float* bn_g   = (const float*)d_in[4];
    const float* bn_b   = (const float*)d_in[5];
    const float* W1     = (const float*)d_in[6];
    const float* b1     = (const float*)d_in[7];
    const float* W2     = (const float*)d_in[8];
    const float* b2     = (const float*)d_in[9];
    const float* W3     = (const float*)d_in[10];
    const float* b3     = (const float*)d_in[11];
    const float* W4     = (const float*)d_in[12];
    const float* b4     = (const float*)d_in[13];
    const float* W5     = (const float*)d_in[14];
    const float* b5     = (const float*)d_in[15];
    const float* W6     = (const float*)d_in[16];
    const float* b6     = (const float*)d_in[17];
    float* out = (float*)d_out;

    cudaFuncSetAttribute(k_pairs_mma, cudaFuncAttributeMaxDynamicSharedMemorySize, DYN_SMEM);

    k_prep<<<(KC*CC + 255)/256, 256>>>(conv_w, W1);
    k_hw<<<BB, 128>>>(h, W1);
    k_conv<<<dim3(10, BB), 256>>>(x, conv_b);
    k_stats_part<<<20, 256>>>();
    k_stats_fin<<<1, 256>>>(bn_g, bn_b);
    k_uv<<<TOK/8, 256>>>();
    k_pairs_mma<<<GRID_PAIRS, 256, DYN_SMEM>>>(W2, W3, W4, b1, b2, b3, b4);
    k_tail<<<BB, 512>>>(W5, b5, W6, b6, out);
}